// round 11
// baseline (speedup 1.0000x reference)
#include <cuda_runtime.h>
#include <math.h>

#define H 1024
#define V 50257
#define L 2
#define NGRP ((V + 7) / 8)     // 6283 row-groups of 8
#define GRID_LOG 720           // <= 5 blocks/SM x 148 SMs -> single co-resident wave

// Scratch (device globals; no allocation allowed; zero-initialized)
__device__ float g_x[H];            // GRU layer 0 output
__device__ float g_y[H];            // GRU layer 1 output (logits input)
__device__ float g_logits[V];
__device__ float g_sumexp;          // sum of exp(logit); reset in gru0
__device__ unsigned g_bar1, g_done1;  // logits kernel barrier (zero-init)

__device__ __forceinline__ float warp_sum(float s) {
    #pragma unroll
    for (int o = 16; o > 0; o >>= 1) s += __shfl_xor_sync(0xFFFFFFFF, s, o);
    return s;
}
__device__ __forceinline__ float sigmoidf_(float v) {
    return 1.0f / (1.0f + __expf(-v));
}

// ---- GRU layer (R6-proven). grid = H blocks, 192 threads (6 warps). ----
template<bool FUSE_EMB>
__global__ __launch_bounds__(192) void gru_layer_kernel(
    const long long* __restrict__ idx,
    const float* __restrict__ emb,
    const float* __restrict__ x_vec,
    const float* __restrict__ h_prev,
    const float* __restrict__ w_ih,
    const float* __restrict__ w_hh,
    const float* __restrict__ b_ih,
    const float* __restrict__ b_hh,
    float* __restrict__ h_out_scratch,
    float* __restrict__ h_out_final)
{
    if (FUSE_EMB && blockIdx.x == 0 && threadIdx.x == 32) {
        g_sumexp = 0.0f;  // reset accumulator each replay (before logits runs)
    }

    int j = blockIdx.x;
    int w = threadIdx.x >> 5;
    int lane = threadIdx.x & 31;

    const float* vec;
    bool do_relu = false;
    if (w < 3) {
        if (FUSE_EMB) { vec = emb + (size_t)idx[0] * H; do_relu = true; }
        else          { vec = x_vec; }
    } else {
        vec = h_prev;
    }
    const float* W = (w < 3) ? w_ih : w_hh;
    int row = (w % 3) * H + j;

    const float4* wr = reinterpret_cast<const float4*>(W + (size_t)row * H);
    const float4* vv = reinterpret_cast<const float4*>(vec);

    float4 a[8], b[8];
    #pragma unroll
    for (int k = 0; k < 8; k++) a[k] = __ldcs(&wr[lane + 32 * k]);
    #pragma unroll
    for (int k = 0; k < 8; k++) b[k] = __ldg(&vv[lane + 32 * k]);
    if (do_relu) {
        #pragma unroll
        for (int k = 0; k < 8; k++) {
            b[k].x = fmaxf(b[k].x, 0.0f); b[k].y = fmaxf(b[k].y, 0.0f);
            b[k].z = fmaxf(b[k].z, 0.0f); b[k].w = fmaxf(b[k].w, 0.0f);
        }
    }
    float s = 0.0f;
    #pragma unroll
    for (int k = 0; k < 8; k++)
        s += a[k].x * b[k].x + a[k].y * b[k].y + a[k].z * b[k].z + a[k].w * b[k].w;
    s = warp_sum(s);

    __shared__ float sm[6];
    if (lane == 0) sm[w] = s;
    __syncthreads();

    if (threadIdx.x == 0) {
        float i_r = sm[0] + b_ih[j];
        float i_z = sm[1] + b_ih[H + j];
        float i_n = sm[2] + b_ih[2 * H + j];
        float h_r = sm[3] + b_hh[j];
        float h_z = sm[4] + b_hh[H + j];
        float h_n = sm[5] + b_hh[2 * H + j];
        float r = sigmoidf_(i_r + h_r);
        float z = sigmoidf_(i_z + h_z);
        float n = tanhf(i_n + r * h_n);
        float hn = (1.0f - z) * n + z * h_prev[j];
        h_out_scratch[j] = hn;
        h_out_final[j]   = hn;
    }
}

// ---- Fused logits + logsoftmax-write. grid = GRID_LOG x 256 threads (8 warps).
// Phase A: warps stream row-groups INDEPENDENTLY (no per-iteration barriers),
// each warp accumulates its own sumexp in registers; one block reduce +
// one atomicAdd at the end. Grid barrier. Phase B: out = logit - log(sumexp). ----
__global__ __launch_bounds__(256, 5) void logits_fused_kernel(
    const float* __restrict__ w_out,
    const float* __restrict__ b_out,
    float* __restrict__ out)
{
    __shared__ float xs[H];
    __shared__ float wacc[8];
    for (int i = threadIdx.x; i < H; i += 256) xs[i] = g_y[i];
    __syncthreads();

    int wid = threadIdx.x >> 5;
    int lane = threadIdx.x & 31;
    const float4* vv = reinterpret_cast<const float4*>(xs);

    float acc = 0.0f;  // per-warp sumexp (all lanes hold same value)
    for (int grp = blockIdx.x; grp < NGRP; grp += GRID_LOG) {
        int row = grp * 8 + wid;
        if (row < V) {
            const float4* wr = reinterpret_cast<const float4*>(
                w_out + (size_t)row * H);
            // weight burst: 8 independent LDG.128 in flight
            float4 a[8];
            #pragma unroll
            for (int k = 0; k < 8; k++) a[k] = __ldcs(&wr[lane + 32 * k]);
            float s = 0.0f;
            #pragma unroll
            for (int k = 0; k < 8; k++) {
                float4 b = vv[lane + 32 * k];   // LDS
                s += a[k].x * b.x + a[k].y * b.y + a[k].z * b.z + a[k].w * b.w;
            }
            s = warp_sum(s);
            float val = s + __ldg(&b_out[row]);
            if (lane == 0) g_logits[row] = val;
            acc += expf(val);                    // same in all lanes
        }
    }

    // block reduce the 8 per-warp accumulators, one atomicAdd
    if (lane == 0) wacc[wid] = acc;
    __syncthreads();
    if (threadIdx.x == 0) {
        float sum = 0.0f;
        #pragma unroll
        for (int k = 0; k < 8; k++) sum += wacc[k];
        atomicAdd(&g_sumexp, sum);
    }

    // ---- grid barrier (single wave: grid <= co-residency) ----
    __syncthreads();
    if (threadIdx.x == 0) {
        __threadfence();                        // publish logits + atomic
        atomicAdd(&g_bar1, 1u);
        while (*(volatile unsigned*)&g_bar1 < GRID_LOG) __nanosleep(64);
    }
    __syncthreads();
    __threadfence();                            // acquire others' writes

    // ---- phase B: write logprobs ----
    float c = logf(*(volatile float*)&g_sumexp);
    const int V4 = V / 4;  // 12564
    for (int i = blockIdx.x * 256 + threadIdx.x; i < V4; i += GRID_LOG * 256) {
        float4 v = reinterpret_cast<const float4*>(g_logits)[i];
        v.x -= c; v.y -= c; v.z -= c; v.w -= c;
        reinterpret_cast<float4*>(out)[i] = v;
    }
    if (blockIdx.x == 0 && threadIdx.x == 0)
        out[V - 1] = g_logits[V - 1] - c;       // tail (V % 4 == 1)

    // reset barrier for next graph replay (last block to finish)
    __syncthreads();
    if (threadIdx.x == 0) {
        unsigned d = atomicAdd(&g_done1, 1u);
        if (d == GRID_LOG - 1) { g_bar1 = 0u; g_done1 = 0u; }
    }
}

extern "C" void kernel_launch(void* const* d_in, const int* in_sizes, int n_in,
                              void* d_out, int out_size) {
    const long long* idx  = (const long long*)d_in[0];
    const float* hidden   = (const float*)d_in[1];
    const float* emb      = (const float*)d_in[2];
    const float* w_ih     = (const float*)d_in[3];
    const float* w_hh     = (const float*)d_in[4];
    const float* b_ih     = (const float*)d_in[5];
    const float* b_hh     = (const float*)d_in[6];
    const float* w_out    = (const float*)d_in[7];
    const float* b_out    = (const float*)d_in[8];

    float* out = (float*)d_out;
    float* out_logprobs = out;       // [V]
    float* out_hidden   = out + V;   // [L, 1, H]

    float* g_x_ptr; cudaGetSymbolAddress((void**)&g_x_ptr, g_x);
    float* g_y_ptr; cudaGetSymbolAddress((void**)&g_y_ptr, g_y);

    gru_layer_kernel<true><<<H, 192>>>(idx, emb, nullptr, hidden,
                                       w_ih, w_hh, b_ih, b_hh,
                                       g_x_ptr, out_hidden);

    gru_layer_kernel<false><<<H, 192>>>(idx, emb, g_x_ptr, hidden + H,
                                        w_ih + 3 * H * H, w_hh + 3 * H * H,
                                        b_ih + 3 * H, b_hh + 3 * H,
                                        g_y_ptr, out_hidden + H);

    logits_fused_kernel<<<GRID_LOG, 256>>>(w_out, b_out, out_logprobs);
}

// round 12
// speedup vs baseline: 1.1179x; 1.1179x over previous
#include <cuda_runtime.h>
#include <math.h>

#define H 1024
#define V 50257
#define L 2
#define ROWS_PB 8
#define NB_LOGITS ((V + ROWS_PB - 1) / ROWS_PB)  // 6283

// Scratch (device globals; no allocation allowed)
__device__ float g_x[H];        // GRU layer 0 output
__device__ float g_y[H];        // GRU layer 1 output (logits input)
__device__ float g_logits[V];
__device__ float g_sumexp;      // accumulated sum of exp(logit); reset by gru0

__device__ __forceinline__ float warp_sum(float s) {
    #pragma unroll
    for (int o = 16; o > 0; o >>= 1) s += __shfl_xor_sync(0xFFFFFFFF, s, o);
    return s;
}
__device__ __forceinline__ float sigmoidf_(float v) {
    return 1.0f / (1.0f + __expf(-v));
}

// ---- GRU layer: 2 output indices per block. grid = H/2, 192 threads (6 warps).
// Warp w handles gate (w%3) on source (w<3 ? x : h) for BOTH j0 and j1:
// 16 independent weight LDG.128 per thread in flight (latency-bound fix).
template<bool FUSE_EMB>
__global__ __launch_bounds__(192) void gru_layer_kernel(
    const long long* __restrict__ idx,
    const float* __restrict__ emb,
    const float* __restrict__ x_vec,
    const float* __restrict__ h_prev,
    const float* __restrict__ w_ih,
    const float* __restrict__ w_hh,
    const float* __restrict__ b_ih,
    const float* __restrict__ b_hh,
    float* __restrict__ h_out_scratch,
    float* __restrict__ h_out_final)
{
    if (FUSE_EMB && blockIdx.x == 0 && threadIdx.x == 32) {
        g_sumexp = 0.0f;  // reset accumulator each replay (before logits runs)
    }

    int j0 = blockIdx.x * 2;
    int j1 = j0 + 1;
    int w = threadIdx.x >> 5;
    int lane = threadIdx.x & 31;

    const float* vec;
    bool do_relu = false;
    if (w < 3) {
        if (FUSE_EMB) { vec = emb + (size_t)idx[0] * H; do_relu = true; }
        else          { vec = x_vec; }
    } else {
        vec = h_prev;
    }
    const float* W = (w < 3) ? w_ih : w_hh;
    int gate = (w % 3);

    const float4* wr0 = reinterpret_cast<const float4*>(W + (size_t)(gate * H + j0) * H);
    const float4* wr1 = reinterpret_cast<const float4*>(W + (size_t)(gate * H + j1) * H);
    const float4* vv  = reinterpret_cast<const float4*>(vec);

    // 16 independent weight loads + 8 vector loads in flight
    float4 a0[8], a1[8], b[8];
    #pragma unroll
    for (int k = 0; k < 8; k++) a0[k] = __ldcs(&wr0[lane + 32 * k]);
    #pragma unroll
    for (int k = 0; k < 8; k++) a1[k] = __ldcs(&wr1[lane + 32 * k]);
    #pragma unroll
    for (int k = 0; k < 8; k++) b[k] = __ldg(&vv[lane + 32 * k]);
    if (do_relu) {
        #pragma unroll
        for (int k = 0; k < 8; k++) {
            b[k].x = fmaxf(b[k].x, 0.0f); b[k].y = fmaxf(b[k].y, 0.0f);
            b[k].z = fmaxf(b[k].z, 0.0f); b[k].w = fmaxf(b[k].w, 0.0f);
        }
    }
    float s0 = 0.0f, s1 = 0.0f;
    #pragma unroll
    for (int k = 0; k < 8; k++) {
        s0 += a0[k].x * b[k].x + a0[k].y * b[k].y + a0[k].z * b[k].z + a0[k].w * b[k].w;
        s1 += a1[k].x * b[k].x + a1[k].y * b[k].y + a1[k].z * b[k].z + a1[k].w * b[k].w;
    }
    s0 = warp_sum(s0);
    s1 = warp_sum(s1);

    __shared__ float sm[6][2];
    if (lane == 0) { sm[w][0] = s0; sm[w][1] = s1; }
    __syncthreads();

    if (threadIdx.x < 2) {
        int j = j0 + threadIdx.x;
        int c = threadIdx.x;
        float i_r = sm[0][c] + b_ih[j];
        float i_z = sm[1][c] + b_ih[H + j];
        float i_n = sm[2][c] + b_ih[2 * H + j];
        float h_r = sm[3][c] + b_hh[j];
        float h_z = sm[4][c] + b_hh[H + j];
        float h_n = sm[5][c] + b_hh[2 * H + j];
        float r = sigmoidf_(i_r + h_r);
        float z = sigmoidf_(i_z + h_z);
        float n = tanhf(i_n + r * h_n);
        float hn = (1.0f - z) * n + z * h_prev[j];
        h_out_scratch[j] = hn;
        h_out_final[j]   = hn;
    }
}

// ---- logits = w_out @ y + b_out; epilogue: one float atomicAdd of block sumexp.
// Logits are tiny (|logit| << 80) so exp() without max-shift is safe/exact. ----
__global__ __launch_bounds__(256) void logits_kernel(
    const float* __restrict__ w_out,
    const float* __restrict__ b_out)
{
    __shared__ float xs[H];
    __shared__ float rowv[ROWS_PB];
    for (int i = threadIdx.x; i < H; i += 256) xs[i] = g_y[i];
    __syncthreads();

    int wid = threadIdx.x >> 5;
    int lane = threadIdx.x & 31;
    int row = blockIdx.x * ROWS_PB + wid;

    float val = 0.0f;
    bool valid = (row < V);
    if (valid) {
        const float4* wr = reinterpret_cast<const float4*>(w_out + (size_t)row * H);
        const float4* vv = reinterpret_cast<const float4*>(xs);

        float4 a[8];
        #pragma unroll
        for (int k = 0; k < 8; k++) a[k] = __ldcs(&wr[lane + 32 * k]);
        float s = 0.0f;
        #pragma unroll
        for (int k = 0; k < 8; k++) {
            float4 b = vv[lane + 32 * k];
            s += a[k].x * b.x + a[k].y * b.y + a[k].z * b.z + a[k].w * b.w;
        }
        s = warp_sum(s);
        if (lane == 0) {
            val = s + b_out[row];
            g_logits[row] = val;
        }
    }
    if (lane == 0) rowv[wid] = valid ? expf(val) : 0.0f;
    __syncthreads();

    // warp 0: sum the 8 per-row exps, single atomicAdd
    if (threadIdx.x < 32) {
        float e = (lane < ROWS_PB) ? rowv[lane] : 0.0f;
        float sum = warp_sum(e);
        if (lane == 0) atomicAdd(&g_sumexp, sum);
    }
}

// ---- write logprobs: out[i] = logits[i] - log(sumexp), float4 wide ----
__global__ __launch_bounds__(256) void write_kernel(float* __restrict__ out) {
    float c = logf(g_sumexp);
    int i = blockIdx.x * 256 + threadIdx.x;
    const int V4 = V / 4;  // 12564
    if (i < V4) {
        float4 v = reinterpret_cast<const float4*>(g_logits)[i];
        v.x -= c; v.y -= c; v.z -= c; v.w -= c;
        reinterpret_cast<float4*>(out)[i] = v;
    }
    if (i == 0) out[V - 1] = g_logits[V - 1] - c;  // tail (V % 4 == 1)
}

extern "C" void kernel_launch(void* const* d_in, const int* in_sizes, int n_in,
                              void* d_out, int out_size) {
    const long long* idx  = (const long long*)d_in[0];
    const float* hidden   = (const float*)d_in[1];
    const float* emb      = (const float*)d_in[2];
    const float* w_ih     = (const float*)d_in[3];
    const float* w_hh     = (const float*)d_in[4];
    const float* b_ih     = (const float*)d_in[5];
    const float* b_hh     = (const float*)d_in[6];
    const float* w_out    = (const float*)d_in[7];
    const float* b_out    = (const float*)d_in[8];

    float* out = (float*)d_out;
    float* out_logprobs = out;       // [V]
    float* out_hidden   = out + V;   // [L, 1, H]

    float* g_x_ptr; cudaGetSymbolAddress((void**)&g_x_ptr, g_x);
    float* g_y_ptr; cudaGetSymbolAddress((void**)&g_y_ptr, g_y);

    gru_layer_kernel<true><<<H / 2, 192>>>(idx, emb, nullptr, hidden,
                                           w_ih, w_hh, b_ih, b_hh,
                                           g_x_ptr, out_hidden);

    gru_layer_kernel<false><<<H / 2, 192>>>(idx, emb, g_x_ptr, hidden + H,
                                            w_ih + 3 * H * H, w_hh + 3 * H * H,
                                            b_ih + 3 * H, b_hh + 3 * H,
                                            g_y_ptr, out_hidden + H);

    logits_kernel<<<NB_LOGITS, 256>>>(w_out, b_out);

    write_kernel<<<(V / 4 + 255) / 256, 256>>>(out_logprobs);
}

// round 13
// speedup vs baseline: 1.1969x; 1.0706x over previous
#include <cuda_runtime.h>
#include <math.h>

#define H 1024
#define V 50257
#define L 2
#define ROWS_PB 8
#define NB_LOGITS ((V + ROWS_PB - 1) / ROWS_PB)  // 6283

// PDL device controls
#define PDL_WAIT()    asm volatile("griddepcontrol.wait;" ::: "memory")
#define PDL_TRIGGER() asm volatile("griddepcontrol.launch_dependents;" ::: "memory")

// Scratch (device globals; no allocation allowed)
__device__ float g_x[H];        // GRU layer 0 output
__device__ float g_y[H];        // GRU layer 1 output (logits input)
__device__ float g_logits[V];
__device__ float g_sumexp;      // accumulated sum of exp(logit); reset by gru0

__device__ __forceinline__ float warp_sum(float s) {
    #pragma unroll
    for (int o = 16; o > 0; o >>= 1) s += __shfl_xor_sync(0xFFFFFFFF, s, o);
    return s;
}
__device__ __forceinline__ float sigmoidf_(float v) {
    return 1.0f / (1.0f + __expf(-v));
}

// ---- GRU layer (R6 shape). grid = H blocks, 192 threads (6 warps). ----
// PDL: weight burst issued BEFORE griddepcontrol.wait (weights independent of
// predecessor); vector loads after. FUSE_EMB layer has no predecessor wait.
template<bool FUSE_EMB>
__global__ __launch_bounds__(192) void gru_layer_kernel(
    const long long* __restrict__ idx,
    const float* __restrict__ emb,
    const float* __restrict__ x_vec,
    const float* __restrict__ h_prev,
    const float* __restrict__ w_ih,
    const float* __restrict__ w_hh,
    const float* __restrict__ b_ih,
    const float* __restrict__ b_hh,
    float* __restrict__ h_out_scratch,
    float* __restrict__ h_out_final)
{
    if (FUSE_EMB && blockIdx.x == 0 && threadIdx.x == 32) {
        g_sumexp = 0.0f;  // reset accumulator each replay (before logits runs)
    }

    int j = blockIdx.x;
    int w = threadIdx.x >> 5;
    int lane = threadIdx.x & 31;

    const float* W = (w < 3) ? w_ih : w_hh;
    int row = (w % 3) * H + j;
    const float4* wr = reinterpret_cast<const float4*>(W + (size_t)row * H);

    // weight burst first: independent of predecessor output
    float4 a[8];
    #pragma unroll
    for (int k = 0; k < 8; k++) a[k] = __ldcs(&wr[lane + 32 * k]);

    if (!FUSE_EMB) PDL_WAIT();   // g_x must be visible before vector loads

    const float* vec;
    bool do_relu = false;
    if (w < 3) {
        if (FUSE_EMB) { vec = emb + (size_t)idx[0] * H; do_relu = true; }
        else          { vec = x_vec; }
    } else {
        vec = h_prev;
    }
    const float4* vv = reinterpret_cast<const float4*>(vec);

    float4 b[8];
    #pragma unroll
    for (int k = 0; k < 8; k++) b[k] = __ldg(&vv[lane + 32 * k]);
    if (do_relu) {
        #pragma unroll
        for (int k = 0; k < 8; k++) {
            b[k].x = fmaxf(b[k].x, 0.0f); b[k].y = fmaxf(b[k].y, 0.0f);
            b[k].z = fmaxf(b[k].z, 0.0f); b[k].w = fmaxf(b[k].w, 0.0f);
        }
    }
    float s = 0.0f;
    #pragma unroll
    for (int k = 0; k < 8; k++)
        s += a[k].x * b[k].x + a[k].y * b[k].y + a[k].z * b[k].z + a[k].w * b[k].w;
    s = warp_sum(s);

    __shared__ float sm[6];
    if (lane == 0) sm[w] = s;
    __syncthreads();

    if (threadIdx.x == 0) {
        float i_r = sm[0] + b_ih[j];
        float i_z = sm[1] + b_ih[H + j];
        float i_n = sm[2] + b_ih[2 * H + j];
        float h_r = sm[3] + b_hh[j];
        float h_z = sm[4] + b_hh[H + j];
        float h_n = sm[5] + b_hh[2 * H + j];
        float r = sigmoidf_(i_r + h_r);
        float z = sigmoidf_(i_z + h_z);
        float n = tanhf(i_n + r * h_n);
        float hn = (1.0f - z) * n + z * h_prev[j];
        h_out_scratch[j] = hn;
        h_out_final[j]   = hn;
    }
    PDL_TRIGGER();   // let the next kernel's blocks launch
}

// ---- logits = w_out @ y + b_out. Weight burst BEFORE wait; then stage y. ----
__global__ __launch_bounds__(256) void logits_kernel(
    const float* __restrict__ w_out,
    const float* __restrict__ b_out)
{
    __shared__ float xs[H];
    __shared__ float rowv[ROWS_PB];

    int wid = threadIdx.x >> 5;
    int lane = threadIdx.x & 31;
    int row = blockIdx.x * ROWS_PB + wid;
    bool valid = (row < V);

    // weight burst first (independent of g_y); OOB row clamped to a safe row
    int lrow = valid ? row : (V - 1);
    const float4* wr = reinterpret_cast<const float4*>(w_out + (size_t)lrow * H);
    float4 a[8];
    #pragma unroll
    for (int k = 0; k < 8; k++) a[k] = __ldcs(&wr[lane + 32 * k]);

    PDL_WAIT();   // g_y (and g_sumexp reset) now visible

    for (int i = threadIdx.x; i < H; i += 256) xs[i] = g_y[i];
    __syncthreads();

    const float4* vv = reinterpret_cast<const float4*>(xs);
    float s = 0.0f;
    #pragma unroll
    for (int k = 0; k < 8; k++) {
        float4 b = vv[lane + 32 * k];
        s += a[k].x * b.x + a[k].y * b.y + a[k].z * b.z + a[k].w * b.w;
    }
    s = warp_sum(s);

    float val = 0.0f;
    if (valid && lane == 0) {
        val = s + b_out[row];
        g_logits[row] = val;
    }
    if (lane == 0) rowv[wid] = valid ? expf(val) : 0.0f;
    __syncthreads();

    // warp 0: sum the 8 per-row exps, single atomicAdd
    if (threadIdx.x < 32) {
        float e = (lane < ROWS_PB) ? rowv[lane] : 0.0f;
        float sum = warp_sum(e);
        if (lane == 0) atomicAdd(&g_sumexp, sum);
    }
    PDL_TRIGGER();
}

// ---- write logprobs: out[i] = logits[i] - log(sumexp), float4 wide ----
__global__ __launch_bounds__(256) void write_kernel(float* __restrict__ out) {
    PDL_WAIT();   // all logits + sumexp visible
    float c = logf(g_sumexp);
    int i = blockIdx.x * 256 + threadIdx.x;
    const int V4 = V / 4;  // 12564
    if (i < V4) {
        float4 v = reinterpret_cast<const float4*>(g_logits)[i];
        v.x -= c; v.y -= c; v.z -= c; v.w -= c;
        reinterpret_cast<float4*>(out)[i] = v;
    }
    if (i == 0) out[V - 1] = g_logits[V - 1] - c;  // tail (V % 4 == 1)
}

// Host-side: launch with PDL attribute so blocks can start (and run their
// pre-wait prologue) while the predecessor kernel is still executing.
template<typename... Args>
static void launch_pdl(void (*kern)(Args...), dim3 grid, dim3 block, Args... args) {
    cudaLaunchConfig_t cfg = {};
    cfg.gridDim = grid;
    cfg.blockDim = block;
    cfg.dynamicSmemBytes = 0;
    cfg.stream = 0;   // same (legacy default) stream as <<<>>> launches
    cudaLaunchAttribute attr[1];
    attr[0].id = cudaLaunchAttributeProgrammaticStreamSerialization;
    attr[0].val.programmaticStreamSerializationAllowed = 1;
    cfg.attrs = attr;
    cfg.numAttrs = 1;
    cudaLaunchKernelEx(&cfg, kern, args...);
}

extern "C" void kernel_launch(void* const* d_in, const int* in_sizes, int n_in,
                              void* d_out, int out_size) {
    const long long* idx  = (const long long*)d_in[0];
    const float* hidden   = (const float*)d_in[1];
    const float* emb      = (const float*)d_in[2];
    const float* w_ih     = (const float*)d_in[3];
    const float* w_hh     = (const float*)d_in[4];
    const float* b_ih     = (const float*)d_in[5];
    const float* b_hh     = (const float*)d_in[6];
    const float* w_out    = (const float*)d_in[7];
    const float* b_out    = (const float*)d_in[8];

    float* out = (float*)d_out;
    float* out_logprobs = out;       // [V]
    float* out_hidden   = out + V;   // [L, 1, H]

    float* g_x_ptr; cudaGetSymbolAddress((void**)&g_x_ptr, g_x);
    float* g_y_ptr; cudaGetSymbolAddress((void**)&g_y_ptr, g_y);

    // GRU layer 0: normal launch (first node)
    gru_layer_kernel<true><<<H, 192>>>(idx, emb, nullptr, hidden,
                                       w_ih, w_hh, b_ih, b_hh,
                                       g_x_ptr, out_hidden);

    // GRU layer 1: PDL — weight loads overlap gru0 tail
    launch_pdl(gru_layer_kernel<false>, dim3(H), dim3(192),
               idx, emb, (const float*)g_x_ptr, hidden + H,
               w_ih + 3 * H * H, w_hh + 3 * H * H,
               b_ih + 3 * H, b_hh + 3 * H,
               g_y_ptr, out_hidden + H);

    // logits: PDL — first-wave weight bursts overlap gru1 tail
    launch_pdl(logits_kernel, dim3(NB_LOGITS), dim3(256), w_out, b_out);

    // write: PDL — launch latency hidden under logits tail
    launch_pdl(write_kernel, dim3((V / 4 + 255) / 256), dim3(256),
               (float*)out_logprobs);
}